// round 12
// baseline (speedup 1.0000x reference)
#include <cuda_runtime.h>
#include <cuda_bf16.h>

// Shapes (fixed): B=32, T=256, D=64, H=128, G=3H=384
#define B 32
#define T 256
#define D 64
#define H 128
#define G 384

// ---------------- scratch (device globals: allocation-free) ----------------
__device__ float g_w[B * D];
__device__ float g_vr[B * T * H];
__device__ float g_gi[B * T * G];

// ---------------- packed f32x2 helpers ----------------
__device__ __forceinline__ unsigned long long ffma2(unsigned long long a,
                                                    unsigned long long b,
                                                    unsigned long long c) {
    unsigned long long d;
    asm("fma.rn.f32x2 %0, %1, %2, %3;" : "=l"(d) : "l"(a), "l"(b), "l"(c));
    return d;
}
__device__ __forceinline__ float2 u2f(unsigned long long v) {
    float2 r;
    asm("mov.b64 {%0, %1}, %2;" : "=f"(r.x), "=f"(r.y) : "l"(v));
    return r;
}
__device__ __forceinline__ float sigf(float x) {
    return __fdividef(1.0f, 1.0f + __expf(-x));
}

// single dynamic-smem symbol (gi_kernel)
extern __shared__ float smdyn[];

// ---------------- kernel 0: prep = sim rows + per-batch w ------------------
__global__ __launch_bounds__(256) void prep_kernel(
    const float* __restrict__ E, const float* __restrict__ mm) {
    __shared__ float Es[D][H + 1];
    __shared__ float simS[D][D + 1];
    __shared__ float part[4][D];
    __shared__ float p[D], rs[D];
    int b = blockIdx.x, tid = threadIdx.x;
    int j = tid & (D - 1), grp = tid >> 6;

    for (int idx = tid; idx < D * H; idx += 256)
        Es[idx >> 7][idx & 127] = E[idx];
    __syncthreads();

    {
        float acc[16] = {};
#pragma unroll 4
        for (int k = 0; k < H; k++) {
            float ej = Es[j][k];
#pragma unroll
            for (int ii = 0; ii < 16; ii++)
                acc[ii] += ej * Es[grp * 16 + ii][k];
        }
#pragma unroll
        for (int ii = 0; ii < 16; ii++)
            simS[j][grp * 16 + ii] = fmaxf(acc[ii], 0.f);
    }

    const float* mb = mm + b * T * D;
    float s = 0.f;
#pragma unroll 8
    for (int t = grp * 64; t < (grp + 1) * 64; t++) s += mb[t * D + j];
    part[grp][j] = s;
    __syncthreads();
    if (tid < D) {
        float tot = part[0][j] + part[1][j] + part[2][j] + part[3][j];
        p[j] = 1.f - tot * (1.f / (float)T);
    }
    __syncthreads();
    if (tid < D) {
        float q = 0.f;
#pragma unroll 8
        for (int jj = 0; jj < D; jj++) q += p[jj] * simS[j][jj];
        rs[j] = fmaxf(p[j] * q + 1.f, 1e-6f);
    }
    __syncthreads();
    if (tid < D) {
        float acc = 0.f;
#pragma unroll 8
        for (int i = 0; i < D; i++) acc += p[i] * simS[j][i] / rs[i];
        g_w[b * D + j] = (p[j] * acc + 1.f / rs[j]) * (1.f / (float)D);
    }
}

// ---------------- kernel 1: visit_repr = c @ E + time_enc ------------------
__global__ __launch_bounds__(256) void vr_kernel(
    const float* __restrict__ x, const float* __restrict__ mm,
    const float* __restrict__ vt, const float* __restrict__ E) {
    __shared__ float Es[D * H];
    __shared__ float cs[32 * D];
    __shared__ float tv[32];
    __shared__ float freqs[64];
    int b = blockIdx.y, t0 = blockIdx.x * 32, tid = threadIdx.x;

    const float NEGC = -0.14391156831212787f;  // -ln(10000)/64
    if (tid < 64) freqs[tid] = __expf(NEGC * (float)tid);
    for (int idx = tid; idx < D * H; idx += 256) Es[idx] = E[idx];
    int base = b * T * D + t0 * D;
    for (int idx = tid; idx < 32 * D; idx += 256) {
        int j = idx & (D - 1);
        cs[idx] = x[base + idx] * (1.f - mm[base + idx]) * g_w[b * D + j];
    }
    if (tid < 32) tv[tid] = vt[b * T + t0 + tid];
    __syncthreads();

    int warp = tid >> 5, lane = tid & 31;
    float acc[4][4] = {};
#pragma unroll 4
    for (int j = 0; j < D; j++) {
        float e0 = Es[j * H + lane];
        float e1 = Es[j * H + lane + 32];
        float e2 = Es[j * H + lane + 64];
        float e3 = Es[j * H + lane + 96];
#pragma unroll
        for (int q = 0; q < 4; q++) {
            float c = cs[(warp * 4 + q) * D + j];
            acc[q][0] += c * e0; acc[q][1] += c * e1;
            acc[q][2] += c * e2; acc[q][3] += c * e3;
        }
    }
#pragma unroll
    for (int q = 0; q < 4; q++) {
        int tt = warp * 4 + q;
        float t = tv[tt];
        float* o = g_vr + (b * T + t0 + tt) * H;
#pragma unroll
        for (int m = 0; m < 4; m++) {
            int h = lane + 32 * m;
            int hm = (h < 64) ? h : h - 64;
            float ang = t * freqs[hm];
            float te = (h < 64) ? sinf(ang) : cosf(ang);
            o[h] = acc[q][m] + te;
        }
    }
}

// ---------------- kernel 2: gi = vr @ W_ih^T + b_ih (+ b_hh for r,z) -------
#define W2STRIDE 130
__global__ __launch_bounds__(256) void gi_kernel(
    const float* __restrict__ wih, const float* __restrict__ bih,
    const float* __restrict__ bhh) {
    float* vrs = smdyn;                                      // 64 x 128 floats
    float2* W2 = reinterpret_cast<float2*>(smdyn + 64 * H);  // [kp][g], str 130
    int bt0 = blockIdx.x * 64, g0 = blockIdx.y * 128, tid = threadIdx.x;

    for (int idx = tid; idx < 64 * H; idx += 256) vrs[idx] = g_vr[bt0 * H + idx];
    const float2* wih2 = reinterpret_cast<const float2*>(wih + g0 * H);
    for (int idx = tid; idx < 128 * 64; idx += 256) {
        int g = idx >> 6, kp = idx & 63;
        W2[kp * W2STRIDE + g] = wih2[g * 64 + kp];
    }
    __syncthreads();

    int warp = tid >> 5, lane = tid & 31;
    const float* vrow = vrs + warp * 8 * H;
    unsigned long long acc[8][4] = {};
#pragma unroll 2
    for (int kp = 0; kp < 64; kp++) {
        const unsigned long long* wrow =
            reinterpret_cast<const unsigned long long*>(W2 + kp * W2STRIDE);
        unsigned long long w0 = wrow[lane];
        unsigned long long w1 = wrow[lane + 32];
        unsigned long long w2 = wrow[lane + 64];
        unsigned long long w3 = wrow[lane + 96];
#pragma unroll
        for (int q = 0; q < 8; q++) {
            unsigned long long v =
                *reinterpret_cast<const unsigned long long*>(vrow + q * H + 2 * kp);
            acc[q][0] = ffma2(w0, v, acc[q][0]);
            acc[q][1] = ffma2(w1, v, acc[q][1]);
            acc[q][2] = ffma2(w2, v, acc[q][2]);
            acc[q][3] = ffma2(w3, v, acc[q][3]);
        }
    }
    bool rz = (g0 < 2 * H);
#pragma unroll
    for (int q = 0; q < 8; q++) {
        float* o = g_gi + (bt0 + warp * 8 + q) * G + g0;
#pragma unroll
        for (int m = 0; m < 4; m++) {
            float2 f = u2f(acc[q][m]);
            int g = lane + 32 * m;
            float bias = bih[g0 + g] + (rz ? bhh[g0 + g] : 0.f);
            o[g] = f.x + f.y + bias;
        }
    }
}

// ---------------- kernel 3: GRU — 2 batches per CTA, shared weights --------
// grid=16, 256 threads. Thread (g = tid>>1, half = tid&1) holds the 3 gate
// rows of W_hh for unit g over its k-half ONCE (192 regs) and runs TWO
// batches' recurrences with them: the second batch's independent FFMA2/LDS/
// MUFU streams fill the first batch's stall slots (latency-bound kernel),
// and the tail + barrier amortize over 2 batch-steps. Gate math identical to
// the R8 champion. h double-buffered per batch; ONE __syncthreads per step.
__global__ __launch_bounds__(256, 1) void gru_kernel(
    const float* __restrict__ whh, const float* __restrict__ bhh,
    const int* __restrict__ lengths, float* __restrict__ out) {
    __shared__ __align__(16) float hs[2][2][136];   // [batch][buf][slot]
    int bp = blockIdx.x;                 // batch pair
    int b0 = 2 * bp;
    int tid = threadIdx.x;
    int g = tid >> 1, half = tid & 1;

    unsigned long long wr[32], wz[32], wn[32];
    {
        const unsigned long long* pr =
            reinterpret_cast<const unsigned long long*>(whh + g * H + half * 64);
        const unsigned long long* pz =
            reinterpret_cast<const unsigned long long*>(whh + (H + g) * H + half * 64);
        const unsigned long long* pn =
            reinterpret_cast<const unsigned long long*>(whh + (2 * H + g) * H + half * 64);
#pragma unroll
        for (int i = 0; i < 32; i++) wr[i] = pr[i];
#pragma unroll
        for (int i = 0; i < 32; i++) wz[i] = pz[i];
#pragma unroll
        for (int i = 0; i < 32; i++) wn[i] = pn[i];
    }
    float bn = bhh[2 * H + g];           // r,z biases pre-folded into g_gi
    int len0 = lengths[b0], len1 = lengths[b0 + 1];
    for (int i = tid; i < 2 * 2 * 136; i += 256)
        (&hs[0][0][0])[i] = 0.f;

    const float* gib0 = g_gi + (size_t)b0 * T * G;
    const float* gib1 = gib0 + (size_t)T * G;
    float* ob0 = out + (size_t)b0 * T * H;
    float* ob1 = ob0 + (size_t)T * H;
    int hidx = (g < 64) ? g : g + 4;

    float gir0 = gib0[g], giz0 = gib0[H + g], gin0 = gib0[2 * H + g];
    float gir1 = gib1[g], giz1 = gib1[H + g], gin1 = gib1[2 * H + g];
    float h0 = 0.f, h1 = 0.f;
    __syncthreads();

    for (int t = 0; t < T; t++) {
        // prefetch next step's gi for both batches (hidden under gemv)
        float pr0 = 0.f, pz0 = 0.f, pn0 = 0.f;
        float pr1 = 0.f, pz1 = 0.f, pn1 = 0.f;
        if (t + 1 < T) {
            const float* qa = gib0 + (t + 1) * G;
            const float* qb = gib1 + (t + 1) * G;
            pr0 = qa[g]; pz0 = qa[H + g]; pn0 = qa[2 * H + g];
            pr1 = qb[g]; pz1 = qb[H + g]; pn1 = qb[2 * H + g];
        }

        const ulonglong2* ha =
            reinterpret_cast<const ulonglong2*>(hs[0][t & 1] + half * 68);
        const ulonglong2* hb =
            reinterpret_cast<const ulonglong2*>(hs[1][t & 1] + half * 68);
        unsigned long long ar0 = 0ull, az0 = 0ull, an0 = 0ull;
        unsigned long long ar1 = 0ull, az1 = 0ull, an1 = 0ull;
#pragma unroll
        for (int i = 0; i < 16; i++) {
            ulonglong2 va = ha[i];                   // broadcast LDS.128
            ulonglong2 vb = hb[i];
            ar0 = ffma2(wr[2 * i], va.x, ar0);
            ar1 = ffma2(wr[2 * i], vb.x, ar1);
            az0 = ffma2(wz[2 * i], va.x, az0);
            az1 = ffma2(wz[2 * i], vb.x, az1);
            an0 = ffma2(wn[2 * i], va.x, an0);
            an1 = ffma2(wn[2 * i], vb.x, an1);
            ar0 = ffma2(wr[2 * i + 1], va.y, ar0);
            ar1 = ffma2(wr[2 * i + 1], vb.y, ar1);
            az0 = ffma2(wz[2 * i + 1], va.y, az0);
            az1 = ffma2(wz[2 * i + 1], vb.y, az1);
            an0 = ffma2(wn[2 * i + 1], va.y, an0);
            an1 = ffma2(wn[2 * i + 1], vb.y, an1);
        }
        float2 f;
        f = u2f(ar0); float sr0 = f.x + f.y;
        f = u2f(az0); float sz0 = f.x + f.y;
        f = u2f(an0); float sn0 = f.x + f.y;
        f = u2f(ar1); float sr1 = f.x + f.y;
        f = u2f(az1); float sz1 = f.x + f.y;
        f = u2f(an1); float sn1 = f.x + f.y;
        sr0 += __shfl_xor_sync(0xffffffffu, sr0, 1);
        sz0 += __shfl_xor_sync(0xffffffffu, sz0, 1);
        sn0 += __shfl_xor_sync(0xffffffffu, sn0, 1);
        sr1 += __shfl_xor_sync(0xffffffffu, sr1, 1);
        sz1 += __shfl_xor_sync(0xffffffffu, sz1, 1);
        sn1 += __shfl_xor_sync(0xffffffffu, sn1, 1);

        // batch 0 gates
        float r0 = sigf(gir0 + sr0);
        float z0 = sigf(giz0 + sz0);
        float a0 = gin0 + r0 * (sn0 + bn);
        float n0 = 1.f - __fdividef(2.f, __expf(2.f * a0) + 1.f);
        float hn0 = n0 + z0 * (h0 - n0);
        h0 = hn0;
        // batch 1 gates
        float r1 = sigf(gir1 + sr1);
        float z1 = sigf(giz1 + sz1);
        float a1 = gin1 + r1 * (sn1 + bn);
        float n1 = 1.f - __fdividef(2.f, __expf(2.f * a1) + 1.f);
        float hn1 = n1 + z1 * (h1 - n1);
        h1 = hn1;

        if (!half) {
            hs[0][(t + 1) & 1][hidx] = hn0;
            hs[1][(t + 1) & 1][hidx] = hn1;
            ob0[t * H + g] = (t < len0) ? hn0 : 0.f;
            ob1[t * H + g] = (t < len1) ? hn1 : 0.f;
        }
        __syncthreads();                             // write -> next read
        gir0 = pr0; giz0 = pz0; gin0 = pn0;
        gir1 = pr1; giz1 = pz1; gin1 = pn1;
    }
}

// ---------------- launcher -------------------------------------------------
extern "C" void kernel_launch(void* const* d_in, const int* in_sizes, int n_in,
                              void* d_out, int out_size) {
    const float* x   = (const float*)d_in[0];
    const float* mm  = (const float*)d_in[1];
    const float* vt  = (const float*)d_in[2];
    const int*   len = (const int*)d_in[4];
    const float* E   = (const float*)d_in[5];
    const float* wih = (const float*)d_in[6];
    const float* whh = (const float*)d_in[7];
    const float* bih = (const float*)d_in[8];
    const float* bhh = (const float*)d_in[9];
    float* out = (float*)d_out;

    size_t gi_smem = 64 * H * sizeof(float) + 64 * W2STRIDE * sizeof(float2);
    cudaFuncSetAttribute(gi_kernel, cudaFuncAttributeMaxDynamicSharedMemorySize,
                         (int)gi_smem);

    prep_kernel<<<B, 256>>>(E, mm);
    vr_kernel<<<dim3(T / 32, B), 256>>>(x, mm, vt, E);
    gi_kernel<<<dim3(B * T / 64, 3), 256, gi_smem>>>(wih, bih, bhh);
    gru_kernel<<<B / 2, 256>>>(whh, bhh, len, out);
}

// round 13
// speedup vs baseline: 1.4091x; 1.4091x over previous
#include <cuda_runtime.h>
#include <cuda_bf16.h>

// Shapes (fixed): B=32, T=256, D=64, H=128, G=3H=384
#define B 32
#define T 256
#define D 64
#define H 128
#define G 384

// ---------------- scratch (device globals: allocation-free) ----------------
__device__ float g_w[B * D];
__device__ float g_vr[B * T * H];
__device__ float g_gi[B * T * G];

// ---------------- packed f32x2 helpers ----------------
__device__ __forceinline__ unsigned long long ffma2(unsigned long long a,
                                                    unsigned long long b,
                                                    unsigned long long c) {
    unsigned long long d;
    asm("fma.rn.f32x2 %0, %1, %2, %3;" : "=l"(d) : "l"(a), "l"(b), "l"(c));
    return d;
}
__device__ __forceinline__ float2 u2f(unsigned long long v) {
    float2 r;
    asm("mov.b64 {%0, %1}, %2;" : "=f"(r.x), "=f"(r.y) : "l"(v));
    return r;
}
__device__ __forceinline__ float sigf(float x) {
    return __fdividef(1.0f, 1.0f + __expf(-x));
}

// single dynamic-smem symbol (gi_kernel)
extern __shared__ float smdyn[];

// ---------------- kernel 0: prep = sim rows + per-batch w ------------------
__global__ __launch_bounds__(256) void prep_kernel(
    const float* __restrict__ E, const float* __restrict__ mm) {
    __shared__ float Es[D][H + 1];
    __shared__ float simS[D][D + 1];
    __shared__ float part[4][D];
    __shared__ float p[D], rs[D];
    int b = blockIdx.x, tid = threadIdx.x;
    int j = tid & (D - 1), grp = tid >> 6;

    for (int idx = tid; idx < D * H; idx += 256)
        Es[idx >> 7][idx & 127] = E[idx];
    __syncthreads();

    {
        float acc[16] = {};
#pragma unroll 4
        for (int k = 0; k < H; k++) {
            float ej = Es[j][k];
#pragma unroll
            for (int ii = 0; ii < 16; ii++)
                acc[ii] += ej * Es[grp * 16 + ii][k];
        }
#pragma unroll
        for (int ii = 0; ii < 16; ii++)
            simS[j][grp * 16 + ii] = fmaxf(acc[ii], 0.f);
    }

    const float* mb = mm + b * T * D;
    float s = 0.f;
#pragma unroll 8
    for (int t = grp * 64; t < (grp + 1) * 64; t++) s += mb[t * D + j];
    part[grp][j] = s;
    __syncthreads();
    if (tid < D) {
        float tot = part[0][j] + part[1][j] + part[2][j] + part[3][j];
        p[j] = 1.f - tot * (1.f / (float)T);
    }
    __syncthreads();
    if (tid < D) {
        float q = 0.f;
#pragma unroll 8
        for (int jj = 0; jj < D; jj++) q += p[jj] * simS[j][jj];
        rs[j] = fmaxf(p[j] * q + 1.f, 1e-6f);
    }
    __syncthreads();
    if (tid < D) {
        float acc = 0.f;
#pragma unroll 8
        for (int i = 0; i < D; i++) acc += p[i] * simS[j][i] / rs[i];
        g_w[b * D + j] = (p[j] * acc + 1.f / rs[j]) * (1.f / (float)D);
    }
}

// ---------------- kernel 1: visit_repr = c @ E + time_enc ------------------
__global__ __launch_bounds__(256) void vr_kernel(
    const float* __restrict__ x, const float* __restrict__ mm,
    const float* __restrict__ vt, const float* __restrict__ E) {
    __shared__ float Es[D * H];
    __shared__ float cs[32 * D];
    __shared__ float tv[32];
    __shared__ float freqs[64];
    int b = blockIdx.y, t0 = blockIdx.x * 32, tid = threadIdx.x;

    const float NEGC = -0.14391156831212787f;  // -ln(10000)/64
    if (tid < 64) freqs[tid] = __expf(NEGC * (float)tid);
    for (int idx = tid; idx < D * H; idx += 256) Es[idx] = E[idx];
    int base = b * T * D + t0 * D;
    for (int idx = tid; idx < 32 * D; idx += 256) {
        int j = idx & (D - 1);
        cs[idx] = x[base + idx] * (1.f - mm[base + idx]) * g_w[b * D + j];
    }
    if (tid < 32) tv[tid] = vt[b * T + t0 + tid];
    __syncthreads();

    int warp = tid >> 5, lane = tid & 31;
    float acc[4][4] = {};
#pragma unroll 4
    for (int j = 0; j < D; j++) {
        float e0 = Es[j * H + lane];
        float e1 = Es[j * H + lane + 32];
        float e2 = Es[j * H + lane + 64];
        float e3 = Es[j * H + lane + 96];
#pragma unroll
        for (int q = 0; q < 4; q++) {
            float c = cs[(warp * 4 + q) * D + j];
            acc[q][0] += c * e0; acc[q][1] += c * e1;
            acc[q][2] += c * e2; acc[q][3] += c * e3;
        }
    }
#pragma unroll
    for (int q = 0; q < 4; q++) {
        int tt = warp * 4 + q;
        float t = tv[tt];
        float* o = g_vr + (b * T + t0 + tt) * H;
#pragma unroll
        for (int m = 0; m < 4; m++) {
            int h = lane + 32 * m;
            int hm = (h < 64) ? h : h - 64;
            float ang = t * freqs[hm];
            float te = (h < 64) ? sinf(ang) : cosf(ang);
            o[h] = acc[q][m] + te;
        }
    }
}

// ---------------- kernel 2: gi = vr @ W_ih^T + biases ----------------------
// g-chunks of 64 (grid 128 x 6): smem 65KB -> 2 CTAs/SM (was 97KB, 1/SM).
#define W2S 66   // float2 stride
__global__ __launch_bounds__(256) void gi_kernel(
    const float* __restrict__ wih, const float* __restrict__ bih,
    const float* __restrict__ bhh) {
    float* vrs = smdyn;                                      // 64 x 128 floats
    float2* W2 = reinterpret_cast<float2*>(smdyn + 64 * H);  // [kp][g], str 66
    int bt0 = blockIdx.x * 64, g0 = blockIdx.y * 64, tid = threadIdx.x;

    for (int idx = tid; idx < 64 * H; idx += 256) vrs[idx] = g_vr[bt0 * H + idx];
    const float2* wih2 = reinterpret_cast<const float2*>(wih + g0 * H);
    for (int idx = tid; idx < 64 * 64; idx += 256) {
        int g = idx >> 6, kp = idx & 63;
        W2[kp * W2S + g] = wih2[g * 64 + kp];
    }
    __syncthreads();

    int warp = tid >> 5, lane = tid & 31;
    const float* vrow = vrs + warp * 8 * H;
    unsigned long long acc[8][2] = {};
#pragma unroll 4
    for (int kp = 0; kp < 64; kp++) {
        const unsigned long long* wrow =
            reinterpret_cast<const unsigned long long*>(W2 + kp * W2S);
        unsigned long long w0 = wrow[lane];
        unsigned long long w1 = wrow[lane + 32];
#pragma unroll
        for (int q = 0; q < 8; q++) {
            unsigned long long v =
                *reinterpret_cast<const unsigned long long*>(vrow + q * H + 2 * kp);
            acc[q][0] = ffma2(w0, v, acc[q][0]);
            acc[q][1] = ffma2(w1, v, acc[q][1]);
        }
    }
    bool rz = (g0 < 2 * H);
#pragma unroll
    for (int q = 0; q < 8; q++) {
        float* o = g_gi + (bt0 + warp * 8 + q) * G + g0;
#pragma unroll
        for (int m = 0; m < 2; m++) {
            float2 f = u2f(acc[q][m]);
            int g = lane + 32 * m;
            float bias = bih[g0 + g] + (rz ? bhh[g0 + g] : 0.f);
            o[g] = f.x + f.y + bias;
        }
    }
}

// ---------------- kernel 3: GRU recurrence (R8 champion, reg-lean) ---------
// 32 blocks x 256 threads, thread (g = tid>>1, half = tid&1) holds all 3 gate
// rows of W_hh over its k-half in registers. h double-buffered; ONE barrier
// per step; 3 SHFL.BFLY(1). Change vs the 163.7us champion: current-step gi
// is loaded at loop top (L2-hit hidden under the 576-cyc gemv) instead of a
// next-step prefetch trio -> ~20 fewer live registers (off the 246-reg
// scheduling cliff), branchless loop top. Gate math bit-identical.
__global__ __launch_bounds__(256, 1) void gru_kernel(
    const float* __restrict__ whh, const float* __restrict__ bhh,
    const int* __restrict__ lengths, float* __restrict__ out) {
    __shared__ __align__(16) float hs[2][136];
    int b = blockIdx.x, tid = threadIdx.x;
    int g = tid >> 1, half = tid & 1;

    unsigned long long wr[32], wz[32], wn[32];
    {
        const unsigned long long* pr =
            reinterpret_cast<const unsigned long long*>(whh + g * H + half * 64);
        const unsigned long long* pz =
            reinterpret_cast<const unsigned long long*>(whh + (H + g) * H + half * 64);
        const unsigned long long* pn =
            reinterpret_cast<const unsigned long long*>(whh + (2 * H + g) * H + half * 64);
#pragma unroll
        for (int i = 0; i < 32; i++) wr[i] = pr[i];
#pragma unroll
        for (int i = 0; i < 32; i++) wz[i] = pz[i];
#pragma unroll
        for (int i = 0; i < 32; i++) wn[i] = pn[i];
    }
    float bn = bhh[2 * H + g];          // r,z biases pre-folded into g_gi
    int len = lengths[b];
    if (tid < 136) { hs[0][tid] = 0.f; hs[1][tid] = 0.f; }

    const float* gib = g_gi + b * T * G;
    float* ob = out + b * T * H;
    int hidx = (g < 64) ? g : g + 4;

    float hreg = 0.f;
    __syncthreads();

#pragma unroll 2
    for (int t = 0; t < T; t++) {
        // current-step gi: issued here, consumed after the gemv (hidden)
        const float* qq = gib + t * G;
        float gir = qq[g], giz = qq[H + g], gin = qq[2 * H + g];

        const ulonglong2* h2 =
            reinterpret_cast<const ulonglong2*>(hs[t & 1] + half * 68);
        unsigned long long ar = 0ull, az = 0ull, an = 0ull;
#pragma unroll
        for (int i = 0; i < 16; i++) {
            ulonglong2 hv = h2[i];                    // broadcast LDS.128
            ar = ffma2(wr[2 * i], hv.x, ar);
            az = ffma2(wz[2 * i], hv.x, az);
            an = ffma2(wn[2 * i], hv.x, an);
            ar = ffma2(wr[2 * i + 1], hv.y, ar);
            az = ffma2(wz[2 * i + 1], hv.y, az);
            an = ffma2(wn[2 * i + 1], hv.y, an);
        }
        float2 fr = u2f(ar), fz = u2f(az), fn = u2f(an);
        float sr = fr.x + fr.y, sz = fz.x + fz.y, sn = fn.x + fn.y;
        sr += __shfl_xor_sync(0xffffffffu, sr, 1);
        sz += __shfl_xor_sync(0xffffffffu, sz, 1);
        sn += __shfl_xor_sync(0xffffffffu, sn, 1);

        float r = sigf(gir + sr);                     // biases pre-folded
        float z = sigf(giz + sz);
        float a = gin + r * (sn + bn);
        float n = 1.f - __fdividef(2.f, __expf(2.f * a) + 1.f);  // fast tanh
        float hn = n + z * (hreg - n);
        hreg = hn;
        if (!half) {
            hs[(t + 1) & 1][hidx] = hn;               // write OTHER buffer
            ob[t * H + g] = (t < len) ? hn : 0.f;
        }
        __syncthreads();                              // write -> next read
    }
}

// ---------------- launcher -------------------------------------------------
extern "C" void kernel_launch(void* const* d_in, const int* in_sizes, int n_in,
                              void* d_out, int out_size) {
    const float* x   = (const float*)d_in[0];
    const float* mm  = (const float*)d_in[1];
    const float* vt  = (const float*)d_in[2];
    const int*   len = (const int*)d_in[4];
    const float* E   = (const float*)d_in[5];
    const float* wih = (const float*)d_in[6];
    const float* whh = (const float*)d_in[7];
    const float* bih = (const float*)d_in[8];
    const float* bhh = (const float*)d_in[9];
    float* out = (float*)d_out;

    size_t gi_smem = 64 * H * sizeof(float) + 64 * W2S * sizeof(float2);
    cudaFuncSetAttribute(gi_kernel, cudaFuncAttributeMaxDynamicSharedMemorySize,
                         (int)gi_smem);

    prep_kernel<<<B, 256>>>(E, mm);
    vr_kernel<<<dim3(T / 32, B), 256>>>(x, mm, vt, E);
    gi_kernel<<<dim3(B * T / 64, 6), 256, gi_smem>>>(wih, bih, bhh);
    gru_kernel<<<B, 256>>>(whh, bhh, len, out);
}